// round 1
// baseline (speedup 1.0000x reference)
#include <cuda_runtime.h>
#include <cuda_fp16.h>
#include <stdint.h>

#define VV 3
#define NN 8192
#define HH 128
#define ADIM 64
#define FOUT 128
#define WORDS (NN/32)
#define SCALE1 256.0f
#define SCALE2 1024.0f

// ---------------- scratch (static device globals; no runtime alloc) ----------------
static __device__ uint32_t g_packed[VV][NN][WORDS];   // 25.2 MB  binary (A+I) mask
static __device__ float    g_dinv[VV][NN];            // D^-1/2
static __device__ __half   g_B16[VV][NN][HH];         // scaled fp16 B operand (reused)
static __device__ float    g_h1[VV][NN][HH];          // layer-1 activations
static __device__ float    g_t[VV][NN][HH];           // h1 @ W2
static __device__ float    g_y1[NN][2*HH];            // fusion hidden
static __device__ float    g_part[VV][8][HH];         // mean-pool partials
static __device__ float    g_summ[VV][HH];
static __device__ float    g_attn[VV];

// ---------------- K1: pack adjacency bits + degrees -------------------------------
__global__ void __launch_bounds__(256) k_pack(const int* __restrict__ adj) {
    const int row = blockIdx.x;
    const int v   = blockIdx.y;
    const int lane = threadIdx.x & 31, warp = threadIdx.x >> 5;
    const int* __restrict__ arow = adj + ((size_t)v*NN + row)*(size_t)NN;
    int cnt = 0;
    for (int w = warp; w < WORDS; w += 8) {
        int col = w*32 + lane;
        bool bit = (col == row) || (arow[col] != 0);
        unsigned m = __ballot_sync(0xffffffffu, bit);
        if (lane == 0) g_packed[v][row][w] = m;
        cnt += bit ? 1 : 0;
    }
    #pragma unroll
    for (int o = 16; o; o >>= 1) cnt += __shfl_xor_sync(0xffffffffu, cnt, o);
    __shared__ int s[8];
    if (lane == 0) s[warp] = cnt;
    __syncthreads();
    if (threadIdx.x == 0) {
        int d = 0;
        #pragma unroll
        for (int i = 0; i < 8; i++) d += s[i];
        g_dinv[v][row] = rsqrtf((float)d);
    }
}

// ---------------- K2/K5: build fp16 B operand = scale * dinv[m] * X[v,m,h] --------
__global__ void k_scale_w1(const float* __restrict__ W) {
    int idx = blockIdx.x * 256 + threadIdx.x;
    if (idx >= VV*NN*HH) return;
    int m = (idx / HH) % NN;
    int v = idx / (NN*HH);
    (&g_B16[0][0][0])[idx] = __float2half(W[idx] * g_dinv[v][m] * SCALE1);
}
__global__ void k_scale_t(int dummy) {
    int idx = blockIdx.x * 256 + threadIdx.x;
    if (idx >= VV*NN*HH) return;
    int m = (idx / HH) % NN;
    int v = idx / (NN*HH);
    (&g_B16[0][0][0])[idx] = __float2half((&g_t[0][0][0])[idx] * g_dinv[v][m] * SCALE2);
    (void)dummy;
}

// ---------------- mma.sync helpers -------------------------------------------------
__device__ __forceinline__ uint32_t smem_u32(const void* p) {
    return (uint32_t)__cvta_generic_to_shared(p);
}
__device__ __forceinline__ void ldsm_x4(uint32_t& r0, uint32_t& r1, uint32_t& r2, uint32_t& r3, uint32_t a) {
    asm volatile("ldmatrix.sync.aligned.m8n8.x4.shared.b16 {%0,%1,%2,%3}, [%4];"
                 : "=r"(r0), "=r"(r1), "=r"(r2), "=r"(r3) : "r"(a));
}
__device__ __forceinline__ void ldsm_x4_t(uint32_t& r0, uint32_t& r1, uint32_t& r2, uint32_t& r3, uint32_t a) {
    asm volatile("ldmatrix.sync.aligned.m8n8.x4.trans.shared.b16 {%0,%1,%2,%3}, [%4];"
                 : "=r"(r0), "=r"(r1), "=r"(r2), "=r"(r3) : "r"(a));
}
__device__ __forceinline__ void mma16816(float* c, const uint32_t* a, const uint32_t* b) {
    asm volatile("mma.sync.aligned.m16n8k16.row.col.f32.f16.f16.f32 "
                 "{%0,%1,%2,%3}, {%4,%5,%6,%7}, {%8,%9}, {%0,%1,%2,%3};"
                 : "+f"(c[0]), "+f"(c[1]), "+f"(c[2]), "+f"(c[3])
                 : "r"(a[0]), "r"(a[1]), "r"(a[2]), "r"(a[3]), "r"(b[0]), "r"(b[1]));
}

// ---------------- K3/K6: out[v,n,h] = relu(dinv[n]*invs*(Bits @ B16) + bias) -------
__global__ void __launch_bounds__(256) k_gemm_masked(const float* __restrict__ bias,
                                                     float* __restrict__ out,
                                                     float invscale) {
    const int v  = blockIdx.y;
    const int n0 = blockIdx.x * 128;
    const int tid = threadIdx.x;
    const int lane = tid & 31, warp = tid >> 5;
    const int wm = warp & 3, wn = warp >> 2;

    __shared__ __half As[128][72];   // 128 rows x 64 k (padded: 144B stride)
    __shared__ __half Bs[64][136];   // 64 k x 128 h   (padded: 272B stride)

    float acc[2][8][4];
    #pragma unroll
    for (int a = 0; a < 2; a++)
        #pragma unroll
        for (int b = 0; b < 8; b++)
            #pragma unroll
            for (int c = 0; c < 4; c++) acc[a][b][c] = 0.f;

    for (int kc = 0; kc < NN; kc += 64) {
        // load B tile (64 x 128 half), vectorized 16B
        #pragma unroll
        for (int c = 0; c < 4; c++) {
            int ch = tid + c*256;
            int kr = ch >> 4, hc = (ch & 15) * 8;
            *(uint4*)&Bs[kr][hc] = *(const uint4*)&g_B16[v][kc + kr][hc];
        }
        // expand A tile from bits: 128 rows x 64 bits -> {0,1} fp16
        {
            int r = tid >> 1, ws = tid & 1;
            uint32_t word = g_packed[v][n0 + r][(kc >> 5) + ws];
            uint32_t* dst = (uint32_t*)&As[r][ws*32];
            #pragma unroll
            for (int j = 0; j < 16; j++) {
                uint32_t val = (((word >> (2*j)) & 1u)   ? 0x00003C00u : 0u)
                             | (((word >> (2*j+1)) & 1u) ? 0x3C000000u : 0u);
                dst[j] = val;
            }
        }
        __syncthreads();

        #pragma unroll
        for (int ks = 0; ks < 4; ks++) {
            const int k = ks * 16;
            uint32_t a[2][4];
            #pragma unroll
            for (int mt = 0; mt < 2; mt++) {
                const __half* p = &As[wm*32 + mt*16 + (lane & 7) + ((lane & 8) ? 8 : 0)]
                                     [k + ((lane & 16) ? 8 : 0)];
                ldsm_x4(a[mt][0], a[mt][1], a[mt][2], a[mt][3], smem_u32(p));
            }
            uint32_t b[8][2];
            #pragma unroll
            for (int nt2 = 0; nt2 < 4; nt2++) {
                int krow = k + (lane & 7) + ((lane & 8) ? 8 : 0);
                int ncol = wn*64 + nt2*16 + ((lane & 16) ? 8 : 0);
                uint32_t r0, r1, r2, r3;
                ldsm_x4_t(r0, r1, r2, r3, smem_u32(&Bs[krow][ncol]));
                b[nt2*2][0] = r0; b[nt2*2][1] = r1;
                b[nt2*2+1][0] = r2; b[nt2*2+1][1] = r3;
            }
            #pragma unroll
            for (int mt = 0; mt < 2; mt++)
                #pragma unroll
                for (int nt = 0; nt < 8; nt++)
                    mma16816(acc[mt][nt], a[mt], b[nt]);
        }
        __syncthreads();
    }

    // epilogue: relu(dinv[n]*invscale*acc + bias[h])
    float* op = out ? out : &g_h1[0][0][0];
    const int g = lane >> 2, cp = (lane & 3) * 2;
    #pragma unroll
    for (int mt = 0; mt < 2; mt++) {
        int r0 = n0 + wm*32 + mt*16 + g;
        float d0 = g_dinv[v][r0] * invscale;
        float d1 = g_dinv[v][r0 + 8] * invscale;
        size_t base0 = ((size_t)v*NN + r0) * HH;
        size_t base1 = ((size_t)v*NN + r0 + 8) * HH;
        #pragma unroll
        for (int nt = 0; nt < 8; nt++) {
            int c0 = wn*64 + nt*8 + cp;
            float b0 = bias[v*HH + c0], b1 = bias[v*HH + c0 + 1];
            op[base0 + c0]     = fmaxf(fmaf(d0, acc[mt][nt][0], b0), 0.f);
            op[base0 + c0 + 1] = fmaxf(fmaf(d0, acc[mt][nt][1], b1), 0.f);
            op[base1 + c0]     = fmaxf(fmaf(d1, acc[mt][nt][2], b0), 0.f);
            op[base1 + c0 + 1] = fmaxf(fmaf(d1, acc[mt][nt][3], b1), 0.f);
        }
    }
}

// ---------------- K4: t = h1 @ W2 (per view, 8192x128 @ 128x128) -------------------
__global__ void __launch_bounds__(128) k_w2(const float* __restrict__ W2) {
    const int v  = blockIdx.y;
    const int n0 = blockIdx.x * 32;
    const int tid = threadIdx.x;                 // = output column h
    __shared__ __half W2s[HH][HH];               // 32 KB
    __shared__ float  h1s[32][HH];               // 16 KB
    for (int i = tid; i < HH*HH; i += 128)
        (&W2s[0][0])[i] = __float2half(W2[(size_t)v*HH*HH + i]);
    for (int r = 0; r < 32; r++)
        h1s[r][tid] = g_h1[v][n0 + r][tid];
    __syncthreads();
    float acc[32];
    #pragma unroll
    for (int r = 0; r < 32; r++) acc[r] = 0.f;
    for (int k = 0; k < HH; k++) {
        float w = __half2float(W2s[k][tid]);
        #pragma unroll
        for (int r = 0; r < 32; r++) acc[r] = fmaf(h1s[r][k], w, acc[r]);
    }
    for (int r = 0; r < 32; r++) g_t[v][n0 + r][tid] = acc[r];
}

// ---------------- K7: mean over nodes (deterministic two-stage) --------------------
__global__ void __launch_bounds__(128) k_part(const float* __restrict__ hmat) {
    const int p = blockIdx.x;      // 0..7
    const int v = blockIdx.y;
    const int h = threadIdx.x;     // 0..127
    float s = 0.f;
    for (int n = p*1024; n < (p+1)*1024; n++)
        s += hmat[((size_t)v*NN + n)*HH + h];
    g_part[v][p][h] = s;
}
__global__ void k_summ() {
    const int v = blockIdx.x, h = threadIdx.x;
    float s = 0.f;
    #pragma unroll
    for (int p = 0; p < 8; p++) s += g_part[v][p][h];
    g_summ[v][h] = s * (1.0f / (float)NN);
}

// ---------------- K8: attention scores + softmax over views ------------------------
__global__ void __launch_bounds__(128) k_attn(const float* __restrict__ Wa1, const float* __restrict__ ba1,
                                              const float* __restrict__ Wa2, const float* __restrict__ ba2,
                                              float* __restrict__ outattn) {
    __shared__ float s1[ADIM];
    __shared__ float sc[VV];
    const int tid = threadIdx.x;
    for (int v = 0; v < VV; v++) {
        if (tid < ADIM) {
            float a = ba1[tid];
            for (int hh = 0; hh < HH; hh++) a = fmaf(g_summ[v][hh], Wa1[hh*ADIM + tid], a);
            s1[tid] = tanhf(a);
        }
        __syncthreads();
        if (tid == 0) {
            float sv = ba2[0];
            for (int j = 0; j < ADIM; j++) sv = fmaf(s1[j], Wa2[j], sv);
            sc[v] = sv;
        }
        __syncthreads();
    }
    if (tid == 0) {
        float m = fmaxf(sc[0], fmaxf(sc[1], sc[2]));
        float e0 = expf(sc[0]-m), e1 = expf(sc[1]-m), e2 = expf(sc[2]-m);
        float inv = 1.f / (e0 + e1 + e2);
        g_attn[0] = e0*inv; g_attn[1] = e1*inv; g_attn[2] = e2*inv;
        outattn[0] = e0*inv; outattn[1] = e1*inv; outattn[2] = e2*inv;
    }
}

// ---------------- K9: y1 = relu([h*attn](N,384) @ Wf1 + bf1) -----------------------
__global__ void __launch_bounds__(256) k_fuse1(const float* __restrict__ hmat,
                                               const float* __restrict__ Wf1,
                                               const float* __restrict__ bf1) {
    const int n0 = blockIdx.x * 32;
    const int tid = threadIdx.x;                 // output column (0..255)
    __shared__ float Xs[32][VV*HH];              // 48 KB
    float a0 = g_attn[0], a1 = g_attn[1], a2 = g_attn[2];
    for (int c = tid; c < 32*VV*HH; c += 256) {
        int r = c / (VV*HH), j = c % (VV*HH);
        int v = j >> 7, h = j & 127;
        float av = (v == 0) ? a0 : ((v == 1) ? a1 : a2);
        Xs[r][j] = hmat[((size_t)v*NN + n0 + r)*HH + h] * av;
    }
    __syncthreads();
    float acc[32];
    #pragma unroll
    for (int r = 0; r < 32; r++) acc[r] = 0.f;
    for (int k = 0; k < VV*HH; k++) {
        float w = Wf1[k*(2*HH) + tid];
        #pragma unroll
        for (int r = 0; r < 32; r++) acc[r] = fmaf(Xs[r][k], w, acc[r]);
    }
    float b = bf1[tid];
    for (int r = 0; r < 32; r++)
        g_y1[n0 + r][tid] = fmaxf(acc[r] + b, 0.f);
}

// ---------------- K10: fused = y1 @ Wf2 + bf2 --------------------------------------
__global__ void __launch_bounds__(128) k_fuse2(const float* __restrict__ Wf2,
                                               const float* __restrict__ bf2,
                                               float* __restrict__ outf) {
    const int n0 = blockIdx.x * 32;
    const int tid = threadIdx.x;                 // output column (0..127)
    __shared__ float Ys[32][2*HH];               // 32 KB
    for (int c = tid; c < 32*2*HH; c += 128)
        Ys[c/(2*HH)][c%(2*HH)] = g_y1[n0 + c/(2*HH)][c%(2*HH)];
    __syncthreads();
    float acc[32];
    #pragma unroll
    for (int r = 0; r < 32; r++) acc[r] = 0.f;
    for (int k = 0; k < 2*HH; k++) {
        float w = Wf2[k*FOUT + tid];
        #pragma unroll
        for (int r = 0; r < 32; r++) acc[r] = fmaf(Ys[r][k], w, acc[r]);
    }
    float b = bf2[tid];
    for (int r = 0; r < 32; r++)
        outf[(size_t)(n0 + r)*FOUT + tid] = acc[r] + b;
}

// ---------------- launch -----------------------------------------------------------
extern "C" void kernel_launch(void* const* d_in, const int* in_sizes, int n_in,
                              void* d_out, int out_size) {
    const int*   adj = (const int*)  d_in[0];
    const float* W1  = (const float*)d_in[1];
    const float* b1  = (const float*)d_in[2];
    const float* W2  = (const float*)d_in[3];
    const float* b2  = (const float*)d_in[4];
    const float* Wa1 = (const float*)d_in[5];
    const float* ba1 = (const float*)d_in[6];
    const float* Wa2 = (const float*)d_in[7];
    const float* ba2 = (const float*)d_in[8];
    const float* Wf1 = (const float*)d_in[9];
    const float* bf1 = (const float*)d_in[10];
    const float* Wf2 = (const float*)d_in[11];
    const float* bf2 = (const float*)d_in[12];

    float* out       = (float*)d_out;
    float* out_fused = out;                                   // (N, F_OUT)
    float* out_attn  = out + (size_t)NN * FOUT;               // (V,)
    float* out_h     = out + (size_t)NN * FOUT + VV;          // (V, N, H)

    // 1. pack adjacency + degrees
    k_pack<<<dim3(NN, VV), 256>>>(adj);
    // 2. B = dinv*W1 (fp16, prescaled)
    k_scale_w1<<<(VV*NN*HH + 255)/256, 256>>>(W1);
    // 3. h1 = relu(dinv[n] * (Bits @ B) + b1)
    k_gemm_masked<<<dim3(NN/128, VV), 256>>>(b1, nullptr, 1.0f/SCALE1);
    // 4. t = h1 @ W2
    k_w2<<<dim3(NN/32, VV), 128>>>(W2);
    // 5. B = dinv*t (fp16, prescaled)
    k_scale_t<<<(VV*NN*HH + 255)/256, 256>>>(0);
    // 6. h = relu(dinv[n] * (Bits @ B) + b2)  -> directly into d_out
    k_gemm_masked<<<dim3(NN/128, VV), 256>>>(b2, out_h, 1.0f/SCALE2);
    // 7. view summaries (mean over nodes), deterministic
    k_part<<<dim3(8, VV), 128>>>(out_h);
    k_summ<<<VV, HH>>>();
    // 8. attention softmax over views
    k_attn<<<1, 128>>>(Wa1, ba1, Wa2, ba2, out_attn);
    // 9/10. fusion MLP
    k_fuse1<<<NN/32, 256>>>(out_h, Wf1, bf1);
    k_fuse2<<<NN/32, 128>>>(Wf2, bf2, out_fused);
}